// round 1
// baseline (speedup 1.0000x reference)
#include <cuda_runtime.h>
#include <math.h>
#include <stdint.h>

#define N_TOK 1024
#define H 2048
#define E 64
#define I_DIM 512
#define TOPK 8
#define CAP 256          // max tokens per expert (counts ~ 128 +- 11; 12-sigma margin)
#define KC 16            // K-chunk per smem stage

// ---------------- scratch (static device globals; zero-initialized) ----------------
__device__ float d_logits[N_TOK * E];
__device__ int   d_topi[N_TOK * TOPK];
__device__ float d_topw[N_TOK * TOPK];
__device__ float d_shg[N_TOK];
__device__ int   d_lists[E * CAP];
__device__ float d_lw[E * CAP];
__device__ int   d_counts[E];
__device__ float d_inter[(size_t)E * CAP * I_DIM];     // 32 MB, padded rows stay 0
__device__ float d_intersh[(size_t)N_TOK * I_DIM];     // 2 MB

// ---------------- helpers ----------------
__device__ __forceinline__ unsigned f2tf(float f) {
    unsigned u;
    asm("cvt.rna.tf32.f32 %0, %1;" : "=r"(u) : "f"(f));
    return u;
}
__device__ __forceinline__ void mma8(float* c, const unsigned* a, const unsigned* b) {
    asm volatile(
        "mma.sync.aligned.m16n8k8.row.col.f32.tf32.tf32.f32 "
        "{%0,%1,%2,%3},{%4,%5,%6,%7},{%8,%9},{%0,%1,%2,%3};"
        : "+f"(c[0]), "+f"(c[1]), "+f"(c[2]), "+f"(c[3])
        : "r"(a[0]), "r"(a[1]), "r"(a[2]), "r"(a[3]), "r"(b[0]), "r"(b[1]));
}
__device__ __forceinline__ void cpa16(void* s, const void* g) {
    unsigned sa = (unsigned)__cvta_generic_to_shared(s);
    asm volatile("cp.async.cg.shared.global [%0], [%1], 16;" :: "r"(sa), "l"(g));
}
__device__ __forceinline__ void cp_commit() { asm volatile("cp.async.commit_group;"); }

// ---------------- K0: routing logits GEMM, full fp32 FFMA ----------------
// logits[n][e] = x[n] . gate_w[e], M=1024 N=64 K=2048. 16 blocks, 64-row tiles.
__global__ __launch_bounds__(256) void k_logits(const float* __restrict__ x,
                                                const float* __restrict__ gw) {
    const int m0 = blockIdx.x * 64;
    __shared__ float As[64][17];
    __shared__ float Bs[64][17];
    const int tid = threadIdx.x;
    const int tr = tid >> 4, tc = tid & 15;
    float acc[4][4] = {};
    const int r = tid >> 2, s4 = (tid & 3) * 4;
    for (int k0 = 0; k0 < H; k0 += 16) {
        float4 av = *(const float4*)(x + (size_t)(m0 + r) * H + k0 + s4);
        float4 bv = *(const float4*)(gw + (size_t)r * H + k0 + s4);
        __syncthreads();
        As[r][s4 + 0] = av.x; As[r][s4 + 1] = av.y; As[r][s4 + 2] = av.z; As[r][s4 + 3] = av.w;
        Bs[r][s4 + 0] = bv.x; Bs[r][s4 + 1] = bv.y; Bs[r][s4 + 2] = bv.z; Bs[r][s4 + 3] = bv.w;
        __syncthreads();
#pragma unroll
        for (int kk = 0; kk < 16; kk++) {
            float a[4], b[4];
#pragma unroll
            for (int i = 0; i < 4; i++) { a[i] = As[tr * 4 + i][kk]; b[i] = Bs[tc * 4 + i][kk]; }
#pragma unroll
            for (int i = 0; i < 4; i++)
#pragma unroll
                for (int j = 0; j < 4; j++) acc[i][j] += a[i] * b[j];
        }
    }
#pragma unroll
    for (int i = 0; i < 4; i++)
#pragma unroll
        for (int j = 0; j < 4; j++)
            d_logits[(size_t)(m0 + tr * 4 + i) * E + tc * 4 + j] = acc[i][j];
}

// ---------------- K1: per-token top-8 + softmax + shared-gate sigmoid ----------------
__global__ __launch_bounds__(64) void k_topk(const float* __restrict__ x,
                                             const float* __restrict__ sh1) {
    const int n = blockIdx.x;
    const int t = threadIdx.x;
    __shared__ float lg[64];
    __shared__ float red[64];
    lg[t] = d_logits[(size_t)n * E + t];
    float p = 0.f;
    const float* xr = x + (size_t)n * H;
    for (int i = t; i < H; i += 64) p += xr[i] * sh1[i];
    red[t] = p;
    __syncthreads();
    if (t == 0) {
        float s = 0.f;
        for (int i = 0; i < 64; i++) s += red[i];
        d_shg[n] = 1.f / (1.f + expf(-s));
        float tmp[64];
        for (int i = 0; i < 64; i++) tmp[i] = lg[i];
        float v[TOPK]; int id[TOPK];
        for (int k = 0; k < TOPK; k++) {
            float bm = -INFINITY; int bi = 0;
            for (int i = 0; i < 64; i++)
                if (tmp[i] > bm) { bm = tmp[i]; bi = i; }
            v[k] = bm; id[k] = bi; tmp[bi] = -INFINITY;
        }
        float mx = v[0], se = 0.f, ev[TOPK];
        for (int k = 0; k < TOPK; k++) { ev[k] = expf(v[k] - mx); se += ev[k]; }
        for (int k = 0; k < TOPK; k++) {
            d_topi[n * TOPK + k] = id[k];
            d_topw[n * TOPK + k] = ev[k] / se;
        }
    }
}

// ---------------- K2: deterministic per-expert compaction ----------------
__global__ __launch_bounds__(256) void k_build() {
    const int e = blockIdx.x, t = threadIdx.x;
    __shared__ int wsum[8];
    __shared__ int base_s;
    if (t == 0) base_s = 0;
    __syncthreads();
    for (int c0 = 0; c0 < N_TOK * TOPK; c0 += 256) {
        int idx = c0 + t;
        int pred = (d_topi[idx] == e) ? 1 : 0;
        unsigned bal = __ballot_sync(0xffffffffu, pred);
        if ((t & 31) == 0) wsum[t >> 5] = __popc(bal);
        __syncthreads();
        int off = 0;
#pragma unroll
        for (int w = 0; w < 8; w++) if (w < (t >> 5)) off += wsum[w];
        int tot = 0;
#pragma unroll
        for (int w = 0; w < 8; w++) tot += wsum[w];
        int pos = base_s + off + __popc(bal & ((1u << (t & 31)) - 1u));
        if (pred && pos < CAP) {
            d_lists[e * CAP + pos] = idx >> 3;   // token index (entries ordered by token)
            d_lw[e * CAP + pos] = d_topw[idx];
        }
        __syncthreads();
        if (t == 0) base_s += tot;
        __syncthreads();
    }
    if (t == 0) d_counts[e] = (base_s > CAP) ? CAP : base_s;
}

// ---------------- K3: fused gate/up tf32 GEMM + silu epilogue ----------------
// blockIdx.x: expert 0..63, or 64 == shared expert. Tile: M=128 x N=64 (per half), K=2048.
__global__ __launch_bounds__(256, 2) void k_gated(const float* __restrict__ x,
                                                  const float* __restrict__ gu_w,
                                                  const float* __restrict__ shg_w,
                                                  const float* __restrict__ shu_w) {
    const int e = blockIdx.x;
    const bool moe = (e < E);
    const int m0 = blockIdx.y * 128;
    const int j0 = blockIdx.z * 64;
    const int cnt = moe ? d_counts[e] : N_TOK;
    if (m0 >= cnt) return;
    const float* Bg = moe ? gu_w + ((size_t)e * 2 * I_DIM + j0) * H : shg_w + (size_t)j0 * H;
    const float* Bu = moe ? gu_w + ((size_t)e * 2 * I_DIM + I_DIM + j0) * H : shu_w + (size_t)j0 * H;

    __shared__ float As[2][128][KC + 4];
    __shared__ float Bs[2][2][64][KC + 4];
    __shared__ int toks[128];
    __shared__ float wr[128];

    const int tid = threadIdx.x;
    for (int r = tid; r < 128; r += 256) {
        int slot = m0 + r;
        if (moe) {
            bool v = slot < cnt;
            toks[r] = v ? d_lists[e * CAP + slot] : 0;
            wr[r]   = v ? d_lw[e * CAP + slot] : 0.f;
        } else {
            toks[r] = slot;
            wr[r] = 1.f;
        }
    }
    __syncthreads();

    auto load_stage = [&](int s) {
        int buf = s & 1, k0 = s * KC;
        for (int c = tid; c < 512; c += 256) {
            int r = c >> 2, seg = c & 3;
            cpa16(&As[buf][r][seg * 4], x + (size_t)toks[r] * H + k0 + seg * 4);
        }
        for (int c = tid; c < 512; c += 256) {
            int hh = c >> 8, rr = (c >> 2) & 63, seg = c & 3;
            const float* src = (hh ? Bu : Bg) + (size_t)rr * H + k0 + seg * 4;
            cpa16(&Bs[buf][hh][rr][seg * 4], src);
        }
        cp_commit();
    };

    float accG[2][4][4] = {}, accU[2][4][4] = {};
    const int warp = tid >> 5, lane = tid & 31;
    const int wm = warp & 3, wn = warp >> 2;
    const int g = lane >> 2, tg = lane & 3;
    const int NS = H / KC;

    load_stage(0);
    for (int s = 0; s < NS; s++) {
        if (s + 1 < NS) { load_stage(s + 1); asm volatile("cp.async.wait_group 1;"); }
        else            { asm volatile("cp.async.wait_group 0;"); }
        __syncthreads();
        const int buf = s & 1;
#pragma unroll
        for (int k8 = 0; k8 < KC / 8; k8++) {
            const int kk = k8 * 8;
            unsigned a[2][4];
#pragma unroll
            for (int mi = 0; mi < 2; mi++) {
                int rb = wm * 32 + mi * 16;
                a[mi][0] = f2tf(As[buf][rb + g][kk + tg]);
                a[mi][1] = f2tf(As[buf][rb + g + 8][kk + tg]);
                a[mi][2] = f2tf(As[buf][rb + g][kk + tg + 4]);
                a[mi][3] = f2tf(As[buf][rb + g + 8][kk + tg + 4]);
            }
            unsigned bg[4][2], bu[4][2];
#pragma unroll
            for (int ni = 0; ni < 4; ni++) {
                int cb = wn * 32 + ni * 8;
                bg[ni][0] = f2tf(Bs[buf][0][cb + g][kk + tg]);
                bg[ni][1] = f2tf(Bs[buf][0][cb + g][kk + tg + 4]);
                bu[ni][0] = f2tf(Bs[buf][1][cb + g][kk + tg]);
                bu[ni][1] = f2tf(Bs[buf][1][cb + g][kk + tg + 4]);
            }
#pragma unroll
            for (int mi = 0; mi < 2; mi++)
#pragma unroll
                for (int ni = 0; ni < 4; ni++) {
                    mma8(accG[mi][ni], a[mi], bg[ni]);
                    mma8(accU[mi][ni], a[mi], bu[ni]);
                }
        }
        __syncthreads();
    }

    // epilogue: inter = silu(gate) * up * route_weight
#pragma unroll
    for (int mi = 0; mi < 2; mi++)
#pragma unroll
        for (int ni = 0; ni < 4; ni++) {
            int rb = wm * 32 + mi * 16, cb = wn * 32 + ni * 8;
#pragma unroll
            for (int hh = 0; hh < 2; hh++) {
                int r = rb + g + hh * 8;
                int slot = m0 + r;
                if (slot < cnt) {
                    float w = wr[r];
                    int col = j0 + cb + 2 * tg;
                    float g0 = accG[mi][ni][hh * 2 + 0], g1 = accG[mi][ni][hh * 2 + 1];
                    float u0 = accU[mi][ni][hh * 2 + 0], u1 = accU[mi][ni][hh * 2 + 1];
                    float v0 = (g0 / (1.f + __expf(-g0))) * u0 * w;
                    float v1 = (g1 / (1.f + __expf(-g1))) * u1 * w;
                    float* dst = moe ? d_inter + ((size_t)e * CAP + slot) * I_DIM
                                     : d_intersh + (size_t)slot * I_DIM;
                    dst[col] = v0;
                    dst[col + 1] = v1;
                }
            }
        }
}

// ---------------- K4: down-projection tf32 GEMM ----------------
// MOE=true: inter[e] @ dp_w[e]^T, atomicAdd scatter to out rows.
// MOE=false: intersh @ sh_down^T, scaled by sigmoid gate, plain store (initializes out).
template <bool MOE>
__global__ __launch_bounds__(256, 2) void k_down(const float* __restrict__ Bsrc,
                                                 float* __restrict__ out) {
    const int e = MOE ? blockIdx.x : 0;
    const int m0 = blockIdx.y * 128, h0 = blockIdx.z * 64;
    const int cnt = MOE ? d_counts[e] : N_TOK;
    if (m0 >= cnt) return;
    const float* A = MOE ? d_inter + (size_t)e * CAP * I_DIM : d_intersh;
    const float* B = MOE ? Bsrc + ((size_t)e * H + h0) * I_DIM : Bsrc + (size_t)h0 * I_DIM;

    __shared__ float As[2][128][KC + 4];
    __shared__ float Bs2[2][64][KC + 4];
    __shared__ int toks[128];
    __shared__ float scl[128];

    const int tid = threadIdx.x;
    for (int r = tid; r < 128; r += 256) {
        int slot = m0 + r;
        if (MOE) toks[r] = (slot < cnt) ? d_lists[e * CAP + slot] : 0;
        else     scl[r] = d_shg[slot];
    }
    __syncthreads();

    auto load_stage = [&](int s) {
        int buf = s & 1, k0 = s * KC;
        for (int c = tid; c < 512; c += 256) {
            int r = c >> 2, seg = c & 3;
            cpa16(&As[buf][r][seg * 4], A + (size_t)(m0 + r) * I_DIM + k0 + seg * 4);
        }
        {
            int c = tid;  // 256 chunks, one per thread
            int rr = c >> 2, seg = c & 3;
            cpa16(&Bs2[buf][rr][seg * 4], B + (size_t)rr * I_DIM + k0 + seg * 4);
        }
        cp_commit();
    };

    float acc[2][4][4] = {};
    const int warp = tid >> 5, lane = tid & 31;
    const int wm = warp & 3, wn = warp >> 2;
    const int g = lane >> 2, tg = lane & 3;
    const int NS = I_DIM / KC;

    load_stage(0);
    for (int s = 0; s < NS; s++) {
        if (s + 1 < NS) { load_stage(s + 1); asm volatile("cp.async.wait_group 1;"); }
        else            { asm volatile("cp.async.wait_group 0;"); }
        __syncthreads();
        const int buf = s & 1;
#pragma unroll
        for (int k8 = 0; k8 < KC / 8; k8++) {
            const int kk = k8 * 8;
            unsigned a[2][4];
#pragma unroll
            for (int mi = 0; mi < 2; mi++) {
                int rb = wm * 32 + mi * 16;
                a[mi][0] = f2tf(As[buf][rb + g][kk + tg]);
                a[mi][1] = f2tf(As[buf][rb + g + 8][kk + tg]);
                a[mi][2] = f2tf(As[buf][rb + g][kk + tg + 4]);
                a[mi][3] = f2tf(As[buf][rb + g + 8][kk + tg + 4]);
            }
            unsigned b[4][2];
#pragma unroll
            for (int ni = 0; ni < 4; ni++) {
                int cb = wn * 32 + ni * 8;
                b[ni][0] = f2tf(Bs2[buf][cb + g][kk + tg]);
                b[ni][1] = f2tf(Bs2[buf][cb + g][kk + tg + 4]);
            }
#pragma unroll
            for (int mi = 0; mi < 2; mi++)
#pragma unroll
                for (int ni = 0; ni < 4; ni++) mma8(acc[mi][ni], a[mi], b[ni]);
        }
        __syncthreads();
    }

#pragma unroll
    for (int mi = 0; mi < 2; mi++)
#pragma unroll
        for (int ni = 0; ni < 4; ni++) {
            int rb = wm * 32 + mi * 16, cb = wn * 32 + ni * 8;
#pragma unroll
            for (int hh = 0; hh < 2; hh++) {
                int r = rb + g + hh * 8;
                int slot = m0 + r;
                int col = h0 + cb + 2 * tg;
                float v0 = acc[mi][ni][hh * 2 + 0];
                float v1 = acc[mi][ni][hh * 2 + 1];
                if (MOE) {
                    if (slot < cnt) {
                        int tk = toks[r];
                        atomicAdd(out + (size_t)tk * H + col, v0);
                        atomicAdd(out + (size_t)tk * H + col + 1, v1);
                    }
                } else {
                    float sc = scl[r];
                    out[(size_t)slot * H + col] = sc * v0;
                    out[(size_t)slot * H + col + 1] = sc * v1;
                }
            }
        }
}

// ---------------- launcher ----------------
extern "C" void kernel_launch(void* const* d_in, const int* in_sizes, int n_in,
                              void* d_out, int out_size) {
    (void)in_sizes; (void)n_in; (void)out_size;
    const float* x      = (const float*)d_in[0];
    const float* gate_w = (const float*)d_in[1];
    const float* gu_w   = (const float*)d_in[2];
    const float* dp_w   = (const float*)d_in[3];
    const float* shg_w  = (const float*)d_in[4];
    const float* shu_w  = (const float*)d_in[5];
    const float* shd_w  = (const float*)d_in[6];
    const float* sh1    = (const float*)d_in[7];
    float* out = (float*)d_out;

    k_logits<<<16, 256>>>(x, gate_w);
    k_topk<<<N_TOK, 64>>>(x, sh1);
    k_build<<<E, 256>>>();
    k_gated<<<dim3(E + 1, 8, 8), 256>>>(x, gu_w, shg_w, shu_w);
    k_down<false><<<dim3(1, 8, 32), 256>>>(shd_w, out);   // init out with shared expert
    k_down<true><<<dim3(E, 8, 32), 256>>>(dp_w, out);     // atomic-accumulate experts
}